// round 12
// baseline (speedup 1.0000x reference)
#include <cuda_runtime.h>
#include <cuda_bf16.h>
#include <cstdint>

#define MAXN 100000
#define MAXE 1200000
#define D 64
#define KD 192
#define MT 64             // node-tile rows per CTA (fused kernel)
#define US 200            // Uhi/Ulo row stride in bf16 (192 + 8 pad)
#define WS 72             // WT row stride in bf16 (64 + 8 pad)
#define SCAN_BLK 1024

// Scratch
__device__ __align__(16) int g_cnt[2 * MAXN];   // per-(half,node) degree
__device__ int   g_off[2 * MAXN];         // scan offsets; after place: bin end
__device__ int   g_eidx[MAXE];            // CSR: src index per edge slot
__device__ int   g_bsum[256];             // scan block aggregates
__device__ int   g_bflag[256];            // aggregate-published flags
__device__ __align__(16) __nv_bfloat16 g_wt[2 * KD * WS];  // [hi|lo] weight tiles
__device__ float g_const[192];            // [K(64) | bO(64) | bI(64)]

// ---------------------------------------------------------------------------
// Truncation bf16 split of a float pair -> packed hi (bf16x2) and lo (bf16x2).
__device__ __forceinline__ void tsplit2(float a, float b, uint32_t& hi, uint32_t& lo) {
    uint32_t ha = __float_as_uint(a) & 0xFFFF0000u;
    uint32_t hb = __float_as_uint(b) & 0xFFFF0000u;
    float la = a - __uint_as_float(ha);
    float lb = b - __uint_as_float(hb);
    hi = __byte_perm(ha, hb, 0x7632);
    lo = __byte_perm(__float_as_uint(la), __float_as_uint(lb), 0x7632);
}

// ---------------------------------------------------------------------------
// Fused init: blocks 0-2 split weights, block 3 consts+flags, blocks 4+ zero g_cnt.
__global__ void init_kernel(const float* __restrict__ W_O, const float* __restrict__ W_I,
                            const float* __restrict__ W_S,
                            const float* __restrict__ b_O, const float* __restrict__ b_I,
                            const float* __restrict__ b_S, const float* __restrict__ r,
                            int nb2) {
    int b = blockIdx.x;
    int t = threadIdx.x;
    if (b < 3) {
        const float* W = (b == 0) ? W_S : (b == 1) ? W_O : W_I;
        unsigned short* gw = reinterpret_cast<unsigned short*>(g_wt);
        for (int idx = t; idx < 1024; idx += 256) {
            int d = idx >> 4, q = idx & 15;
            float4 w = __ldg(reinterpret_cast<const float4*>(W + d * 64) + q);
            int kb = b * 64 + q * 4;
            float vs[4] = { w.x, w.y, w.z, w.w };
            #pragma unroll
            for (int j = 0; j < 4; j++) {
                uint32_t h = __float_as_uint(vs[j]) & 0xFFFF0000u;
                float l = vs[j] - __uint_as_float(h);
                gw[(kb + j) * WS + d] = (unsigned short)(h >> 16);
                gw[KD * WS + (kb + j) * WS + d] = (unsigned short)(__float_as_uint(l) >> 16);
            }
        }
    } else if (b == 3) {
        g_bflag[t] = 0;                      // reset lookback flags every call
        if (t < 64) {
            float acc = b_S[t];
            const float* wrow = W_S + t * 64;
            #pragma unroll 8
            for (int k = 0; k < 64; k++) acc -= r[k] * wrow[k];
            g_const[t] = acc;
        } else if (t < 128) {
            g_const[t] = b_O[t - 64];
        } else if (t < 192) {
            g_const[t] = b_I[t - 128];
        }
    } else {
        int i4 = (b - 4) * 256 + t;          // int4 index
        int4* c4 = reinterpret_cast<int4*>(g_cnt);
        if (i4 * 4 < nb2) c4[i4] = make_int4(0, 0, 0, 0);
    }
}

// ---------------------------------------------------------------------------
__global__ void hist_kernel(const int* __restrict__ dst, int E, int half, int n) {
    int e = blockIdx.x * blockDim.x + threadIdx.x;
    if (e >= E) return;
    int d = __ldg(dst + e);
    int bin = (e >= half) ? (n + d) : d;
    atomicAdd(&g_cnt[bin], 1);
}

// ---------------------------------------------------------------------------
// Fused single-pass scan (decoupled lookback, publish-before-wait).
__global__ void scan_fused(int nb2) {
    __shared__ int warp_sums[8];
    __shared__ int wbase[8];
    __shared__ int red[8];
    __shared__ int sbase;
    int t = threadIdx.x;
    int b = blockIdx.x;
    int lane = t & 31, wid = t >> 5;
    int base = b * SCAN_BLK;
    int idx0 = base + t * 4;

    int v[4];
    #pragma unroll
    for (int j = 0; j < 4; j++) {
        int i = idx0 + j;
        v[j] = (i < nb2) ? g_cnt[i] : 0;
    }
    int s = v[0] + v[1] + v[2] + v[3];
    int sc = s;
    #pragma unroll
    for (int o = 1; o < 32; o <<= 1) {
        int u = __shfl_up_sync(0xFFFFFFFFu, sc, o);
        if (lane >= o) sc += u;
    }
    if (lane == 31) warp_sums[wid] = sc;
    __syncthreads();
    if (t == 0) {
        int run = 0;
        #pragma unroll
        for (int w = 0; w < 8; w++) { wbase[w] = run; run += warp_sums[w]; }
        g_bsum[b] = run;
        __threadfence();
        atomicExch(&g_bflag[b], 1);          // publish aggregate
    }

    int contrib = 0;
    if (t < b) {
        while (atomicAdd(&g_bflag[t], 0) == 0) {}
        __threadfence();
        contrib = g_bsum[t];
    }
    #pragma unroll
    for (int o = 16; o > 0; o >>= 1) contrib += __shfl_down_sync(0xFFFFFFFFu, contrib, o);
    if (lane == 0) red[wid] = contrib;
    __syncthreads();
    if (t == 0) {
        int ss = 0;
        #pragma unroll
        for (int w = 0; w < 8; w++) ss += red[w];
        sbase = ss;
    }
    __syncthreads();

    int run = sbase + wbase[wid] + (sc - s);
    #pragma unroll
    for (int j = 0; j < 4; j++) {
        int i = idx0 + j;
        if (i < nb2) g_off[i] = run;
        run += v[j];
    }
}

// ---------------------------------------------------------------------------
// place: g_off doubles as cursor; after this kernel g_off[bin] == bin end.
__global__ void place_kernel(const int* __restrict__ src,
                             const int* __restrict__ dst,
                             int E, int half, int n) {
    int e = blockIdx.x * blockDim.x + threadIdx.x;
    if (e >= E) return;
    int s = __ldg(src + e);
    int d = __ldg(dst + e);
    int bin = (e >= half) ? (n + d) : d;
    int pos = atomicAdd(&g_off[bin], 1);
    g_eidx[pos] = s;
}

// ---------------------------------------------------------------------------
__device__ __forceinline__ uint32_t sptr(const void* p) {
    return (uint32_t)__cvta_generic_to_shared(p);
}
__device__ __forceinline__ void ldsm_x4(uint32_t& r0, uint32_t& r1, uint32_t& r2, uint32_t& r3,
                                        uint32_t addr) {
    asm volatile("ldmatrix.sync.aligned.m8n8.x4.shared.b16 {%0,%1,%2,%3}, [%4];"
                 : "=r"(r0), "=r"(r1), "=r"(r2), "=r"(r3) : "r"(addr));
}
__device__ __forceinline__ void ldsm_x4_t(uint32_t& r0, uint32_t& r1, uint32_t& r2, uint32_t& r3,
                                          uint32_t addr) {
    asm volatile("ldmatrix.sync.aligned.m8n8.x4.trans.shared.b16 {%0,%1,%2,%3}, [%4];"
                 : "=r"(r0), "=r"(r1), "=r"(r2), "=r"(r3) : "r"(addr));
}
__device__ __forceinline__ void mma_bf16(float* c, uint32_t a0, uint32_t a1, uint32_t a2, uint32_t a3,
                                         uint32_t b0, uint32_t b1) {
    asm volatile("mma.sync.aligned.m16n8k16.row.col.f32.bf16.bf16.f32 "
                 "{%0,%1,%2,%3}, {%4,%5,%6,%7}, {%8,%9}, {%0,%1,%2,%3};"
                 : "+f"(c[0]), "+f"(c[1]), "+f"(c[2]), "+f"(c[3])
                 : "r"(a0), "r"(a1), "r"(a2), "r"(a3), "r"(b0), "r"(b1));
}

// Per-warp CSR bin gather: sum x rows over bin's edge list. Lane owns cols
// [2*lane, 2*lane+1]. Broadcast idx loads + MLP-4 independent row loads.
__device__ __forceinline__ float2 gather_bin(const float2* __restrict__ xp,
                                             int bin, int lane, int deg, int off) {
    float2 a0 = make_float2(0.f, 0.f), a1 = a0, a2 = a0, a3 = a0;
    int i = 0;
    for (; i + 3 < deg; i += 4) {
        int s0 = __ldg(g_eidx + off + i);
        int s1 = __ldg(g_eidx + off + i + 1);
        int s2 = __ldg(g_eidx + off + i + 2);
        int s3 = __ldg(g_eidx + off + i + 3);
        float2 v0 = __ldg(xp + (size_t)s0 * 32 + lane);
        float2 v1 = __ldg(xp + (size_t)s1 * 32 + lane);
        float2 v2 = __ldg(xp + (size_t)s2 * 32 + lane);
        float2 v3 = __ldg(xp + (size_t)s3 * 32 + lane);
        a0.x += v0.x; a0.y += v0.y;
        a1.x += v1.x; a1.y += v1.y;
        a2.x += v2.x; a2.y += v2.y;
        a3.x += v3.x; a3.y += v3.y;
    }
    if (i + 1 < deg) {
        int s0 = __ldg(g_eidx + off + i);
        int s1 = __ldg(g_eidx + off + i + 1);
        float2 v0 = __ldg(xp + (size_t)s0 * 32 + lane);
        float2 v1 = __ldg(xp + (size_t)s1 * 32 + lane);
        a0.x += v0.x; a0.y += v0.y;
        a1.x += v1.x; a1.y += v1.y;
        i += 2;
    }
    if (i < deg) {
        int s0 = __ldg(g_eidx + off + i);
        float2 v0 = __ldg(xp + (size_t)s0 * 32 + lane);
        a0.x += v0.x; a0.y += v0.y;
    }
    a0.x += a1.x + a2.x + a3.x;
    a0.y += a1.y + a2.y + a3.y;
    return a0;
}

// ---------------------------------------------------------------------------
// FUSED node kernel: per-warp CSR gather -> fixup -> trunc-split -> smem U,
// then tensor-core MMA. No g_acc round trip. Last block computes r_out.
__global__ void node_fused_kernel(const float* __restrict__ x,
                                  const float* __restrict__ r,
                                  const float* __restrict__ W_R, const float* __restrict__ b_R,
                                  float* __restrict__ out, int n) {
    int tid = threadIdx.x;

    if (blockIdx.x == gridDim.x - 1) {   // r_out block
        if (tid < 64) {
            float acc = b_R[tid];
            const float* wrow = W_R + tid * 64;
            #pragma unroll 8
            for (int k = 0; k < 64; k++) acc += r[k] * wrow[k];
            out[(size_t)n * D + tid] = acc;
        }
        return;
    }

    extern __shared__ __align__(16) char smraw[];
    __nv_bfloat16* WThi = (__nv_bfloat16*)smraw;            // [192][WS]
    __nv_bfloat16* WTlo = WThi + KD * WS;                   // [192][WS]
    __nv_bfloat16* Uhi  = WTlo + KD * WS;                   // [MT][US]
    __nv_bfloat16* Ulo  = Uhi + MT * US;                    // [MT][US]
    float* Ksm = (float*)(Ulo + MT * US);                   // [64] then bOs, bIs
    float* bOs = Ksm + 64;
    float* bIs = bOs + 64;
    float* cOs = bIs + 64;                                  // [64]
    float* cIs = cOs + 64;                                  // [64]

    int node0 = blockIdx.x * MT;
    int warp = tid >> 5, lane = tid & 31;
    int wr0 = warp * 16;

    // ---- phase 1 (cooperative): stage prepped split weights + consts ----
    {
        const uint4* srcw = reinterpret_cast<const uint4*>(g_wt);
        uint4* dstw = reinterpret_cast<uint4*>(WThi);       // WThi|WTlo contiguous
        #pragma unroll 4
        for (int i = tid; i < (2 * KD * WS) / 8; i += 128) dstw[i] = srcw[i];
    }
    for (int i = tid; i < 192; i += 128) Ksm[i] = g_const[i];
    __syncthreads();

    // ---- phase 2 (per-warp): gather own 16 rows' bins, fixup, split to smem ----
    {
        const float2* xp = reinterpret_cast<const float2*>(x);
        for (int rr = 0; rr < 16; rr++) {
            int row = wr0 + rr;
            int nn = node0 + row;
            float2 vx = make_float2(0.f, 0.f), sO = vx, sI = vx;
            float cO = 0.f, cI = 0.f;
            if (nn < n) {
                int degO = __ldg(&g_cnt[nn]);
                int degI = __ldg(&g_cnt[n + nn]);
                int offO = __ldg(&g_off[nn]) - degO;
                int offI = __ldg(&g_off[n + nn]) - degI;
                vx = __ldg(xp + (size_t)nn * 32 + lane);
                sO = gather_bin(xp, nn, lane, degO, offO);
                sI = gather_bin(xp, n + nn, lane, degI, offI);
                cO = (float)degO;
                cI = (float)degI;
            }
            float2 uO = make_float2(sO.x - cO * vx.x, sO.y - cO * vx.y);
            float2 uI = make_float2(sI.x - cI * vx.x, sI.y - cI * vx.y);
            uint32_t* UhiR = reinterpret_cast<uint32_t*>(Uhi + row * US);
            uint32_t* UloR = reinterpret_cast<uint32_t*>(Ulo + row * US);
            uint32_t hh, ll;
            tsplit2(vx.x, vx.y, hh, ll); UhiR[lane] = hh;      UloR[lane] = ll;
            tsplit2(uO.x, uO.y, hh, ll); UhiR[32 + lane] = hh; UloR[32 + lane] = ll;
            tsplit2(uI.x, uI.y, hh, ll); UhiR[64 + lane] = hh; UloR[64 + lane] = ll;
            if (lane == 0) { cOs[row] = cO; cIs[row] = cI; }
        }
    }
    __syncwarp();   // A rows are warp-private; weights synced in phase 1

    // ---- phase 3: MMA mainloop (identical to proven R9/R11 form) ----
    float acc[8][4];
    #pragma unroll
    for (int i = 0; i < 8; i++)
        #pragma unroll
        for (int j = 0; j < 4; j++) acc[i][j] = 0.f;

    int lrow = lane & 15;
    int lcol = (lane >> 4) * 8;
    uint32_t aHiBase = sptr(Uhi + (wr0 + lrow) * US + lcol);
    uint32_t aLoBase = sptr(Ulo + (wr0 + lrow) * US + lcol);
    uint32_t bHiBase = sptr(WThi + lrow * WS + lcol);
    uint32_t bLoBase = sptr(WTlo + lrow * WS + lcol);

    for (int ks = 0; ks < KD / 16; ks++) {
        uint32_t koffA = ks * 16 * 2;
        uint32_t koffB = (uint32_t)(ks * 16 * WS) * 2;

        uint32_t ah0, ah1, ah2, ah3, al0, al1, al2, al3;
        ldsm_x4(ah0, ah1, ah2, ah3, aHiBase + koffA);
        ldsm_x4(al0, al1, al2, al3, aLoBase + koffA);

        uint32_t bh[4][4], bl[4][4];
        #pragma unroll
        for (int p = 0; p < 4; p++) {
            uint32_t cofs = (uint32_t)(p * 16) * 2;
            ldsm_x4_t(bh[p][0], bh[p][1], bh[p][2], bh[p][3], bHiBase + koffB + cofs);
            ldsm_x4_t(bl[p][0], bl[p][1], bl[p][2], bl[p][3], bLoBase + koffB + cofs);
        }

        #pragma unroll
        for (int p = 0; p < 4; p++) {
            mma_bf16(acc[2 * p],     ah0, ah1, ah2, ah3, bh[p][0], bh[p][1]);
            mma_bf16(acc[2 * p + 1], ah0, ah1, ah2, ah3, bh[p][2], bh[p][3]);
        }
        #pragma unroll
        for (int p = 0; p < 4; p++) {
            mma_bf16(acc[2 * p],     ah0, ah1, ah2, ah3, bl[p][0], bl[p][1]);
            mma_bf16(acc[2 * p + 1], ah0, ah1, ah2, ah3, bl[p][2], bl[p][3]);
        }
        #pragma unroll
        for (int p = 0; p < 4; p++) {
            mma_bf16(acc[2 * p],     al0, al1, al2, al3, bh[p][0], bh[p][1]);
            mma_bf16(acc[2 * p + 1], al0, al1, al2, al3, bh[p][2], bh[p][3]);
        }
    }

    // ---- epilogue ----
    int rl0 = wr0 + (lane >> 2);
    int rl1 = rl0 + 8;
    int nn0 = node0 + rl0;
    int nn1 = node0 + rl1;
    float cO0 = cOs[rl0], cI0 = cIs[rl0];
    float cO1 = cOs[rl1], cI1 = cIs[rl1];
    int ecol = (lane & 3) * 2;

    #pragma unroll
    for (int nt = 0; nt < 8; nt++) {
        int c = nt * 8 + ecol;
        float k0v = Ksm[c],  k1v = Ksm[c + 1];
        float bo0 = bOs[c],  bo1 = bOs[c + 1];
        float bi0 = bIs[c],  bi1 = bIs[c + 1];
        if (nn0 < n) {
            float2 o;
            o.x = acc[nt][0] + k0v + cO0 * bo0 + cI0 * bi0;
            o.y = acc[nt][1] + k1v + cO0 * bo1 + cI0 * bi1;
            *reinterpret_cast<float2*>(out + (size_t)nn0 * D + c) = o;
        }
        if (nn1 < n) {
            float2 o;
            o.x = acc[nt][2] + k0v + cO1 * bo0 + cI1 * bi0;
            o.y = acc[nt][3] + k1v + cO1 * bo1 + cI1 * bi1;
            *reinterpret_cast<float2*>(out + (size_t)nn1 * D + c) = o;
        }
    }
}

// ---------------------------------------------------------------------------
extern "C" void kernel_launch(void* const* d_in, const int* in_sizes, int n_in,
                              void* d_out, int out_size) {
    const float* x   = (const float*)d_in[0];
    const float* r   = (const float*)d_in[1];
    const int*   src = (const int*)d_in[2];
    const int*   dst = (const int*)d_in[3];
    const float* W_O = (const float*)d_in[4];
    const float* b_O = (const float*)d_in[5];
    const float* W_I = (const float*)d_in[6];
    const float* b_I = (const float*)d_in[7];
    const float* W_S = (const float*)d_in[8];
    const float* b_S = (const float*)d_in[9];
    const float* W_R = (const float*)d_in[10];
    const float* b_R = (const float*)d_in[11];
    float* out = (float*)d_out;

    int n = in_sizes[0] / D;       // 100000
    int E = in_sizes[2];           // 1200000
    int half = E / 2;
    int nb2 = 2 * n;
    int nscan = (nb2 + SCAN_BLK - 1) / SCAN_BLK;   // 196

    const int SMEM_BYTES = (2 * KD * WS + 2 * MT * US) * (int)sizeof(__nv_bfloat16)
                         + 5 * 64 * (int)sizeof(float);
    cudaFuncSetAttribute(node_fused_kernel, cudaFuncAttributeMaxDynamicSharedMemorySize, SMEM_BYTES);

    int zblocks = (nb2 / 4 + 255) / 256;           // int4-zero blocks
    init_kernel<<<4 + zblocks, 256>>>(W_O, W_I, W_S, b_O, b_I, b_S, r, nb2);
    hist_kernel<<<(E + 255) / 256, 256>>>(dst, E, half, n);
    scan_fused<<<nscan, 256>>>(nb2);
    place_kernel<<<(E + 255) / 256, 256>>>(src, dst, E, half, n);

    int nblocks = (n + MT - 1) / MT + 1;   // +1 for r_out
    node_fused_kernel<<<nblocks, 128, SMEM_BYTES>>>(x, r, W_R, b_R, out, n);
}

// round 13
// speedup vs baseline: 1.5750x; 1.5750x over previous
#include <cuda_runtime.h>
#include <cuda_bf16.h>
#include <cstdint>

#define MAXN 100000
#define MAXE 1200000
#define D 64
#define KD 192
#define MT 128            // node-tile rows per CTA (node kernel, 8 warps x 16 rows)
#define US 200            // Uhi/Ulo row stride in bf16 (192 + 8 pad)
#define WS 72             // WT row stride in bf16 (64 + 8 pad)
#define SCAN_BLK 1024

// Scratch
__device__ float g_acc[2UL * MAXN * D];   // gather results [2][N][64]
__device__ __align__(16) int g_cnt[2 * MAXN];   // per-(half,node) degree
__device__ int   g_off[2 * MAXN];         // scan offsets; after place: bin end
__device__ int   g_eidx[MAXE];            // CSR: src index per edge slot
__device__ int   g_bsum[256];             // scan block aggregates
__device__ int   g_bflag[256];            // aggregate-published flags
__device__ __align__(16) __nv_bfloat16 g_wt[2 * KD * WS];  // [hi|lo] weight tiles
__device__ float g_const[192];            // [K(64) | bO(64) | bI(64)]

// ---------------------------------------------------------------------------
// Truncation bf16 split of a float pair -> packed hi (bf16x2) and lo (bf16x2).
__device__ __forceinline__ void tsplit2(float a, float b, uint32_t& hi, uint32_t& lo) {
    uint32_t ha = __float_as_uint(a) & 0xFFFF0000u;
    uint32_t hb = __float_as_uint(b) & 0xFFFF0000u;
    float la = a - __uint_as_float(ha);
    float lb = b - __uint_as_float(hb);
    hi = __byte_perm(ha, hb, 0x7632);
    lo = __byte_perm(__float_as_uint(la), __float_as_uint(lb), 0x7632);
}

// ---------------------------------------------------------------------------
// Fused init: blocks 0-2 split weights, block 3 consts+flags, blocks 4+ zero g_cnt.
__global__ void init_kernel(const float* __restrict__ W_O, const float* __restrict__ W_I,
                            const float* __restrict__ W_S,
                            const float* __restrict__ b_O, const float* __restrict__ b_I,
                            const float* __restrict__ b_S, const float* __restrict__ r,
                            int nb2) {
    int b = blockIdx.x;
    int t = threadIdx.x;
    if (b < 3) {
        const float* W = (b == 0) ? W_S : (b == 1) ? W_O : W_I;
        unsigned short* gw = reinterpret_cast<unsigned short*>(g_wt);
        for (int idx = t; idx < 1024; idx += 256) {
            int d = idx >> 4, q = idx & 15;
            float4 w = __ldg(reinterpret_cast<const float4*>(W + d * 64) + q);
            int kb = b * 64 + q * 4;
            float vs[4] = { w.x, w.y, w.z, w.w };
            #pragma unroll
            for (int j = 0; j < 4; j++) {
                uint32_t h = __float_as_uint(vs[j]) & 0xFFFF0000u;
                float l = vs[j] - __uint_as_float(h);
                gw[(kb + j) * WS + d] = (unsigned short)(h >> 16);
                gw[KD * WS + (kb + j) * WS + d] = (unsigned short)(__float_as_uint(l) >> 16);
            }
        }
    } else if (b == 3) {
        g_bflag[t] = 0;                      // reset lookback flags every call
        if (t < 64) {
            float acc = b_S[t];
            const float* wrow = W_S + t * 64;
            #pragma unroll 8
            for (int k = 0; k < 64; k++) acc -= r[k] * wrow[k];
            g_const[t] = acc;
        } else if (t < 128) {
            g_const[t] = b_O[t - 64];
        } else if (t < 192) {
            g_const[t] = b_I[t - 128];
        }
    } else {
        int i4 = (b - 4) * 256 + t;          // int4 index
        int4* c4 = reinterpret_cast<int4*>(g_cnt);
        if (i4 * 4 < nb2) c4[i4] = make_int4(0, 0, 0, 0);
    }
}

// ---------------------------------------------------------------------------
__global__ void hist_kernel(const int* __restrict__ dst, int E, int half, int n) {
    int e = blockIdx.x * blockDim.x + threadIdx.x;
    if (e >= E) return;
    int d = __ldg(dst + e);
    int bin = (e >= half) ? (n + d) : d;
    atomicAdd(&g_cnt[bin], 1);
}

// ---------------------------------------------------------------------------
// Fused single-pass scan (decoupled lookback, publish-before-wait).
__global__ void scan_fused(int nb2) {
    __shared__ int warp_sums[8];
    __shared__ int wbase[8];
    __shared__ int red[8];
    __shared__ int sbase;
    int t = threadIdx.x;
    int b = blockIdx.x;
    int lane = t & 31, wid = t >> 5;
    int base = b * SCAN_BLK;
    int idx0 = base + t * 4;

    int v[4];
    #pragma unroll
    for (int j = 0; j < 4; j++) {
        int i = idx0 + j;
        v[j] = (i < nb2) ? g_cnt[i] : 0;
    }
    int s = v[0] + v[1] + v[2] + v[3];
    int sc = s;
    #pragma unroll
    for (int o = 1; o < 32; o <<= 1) {
        int u = __shfl_up_sync(0xFFFFFFFFu, sc, o);
        if (lane >= o) sc += u;
    }
    if (lane == 31) warp_sums[wid] = sc;
    __syncthreads();
    if (t == 0) {
        int run = 0;
        #pragma unroll
        for (int w = 0; w < 8; w++) { wbase[w] = run; run += warp_sums[w]; }
        g_bsum[b] = run;
        __threadfence();
        atomicExch(&g_bflag[b], 1);          // publish aggregate
    }

    int contrib = 0;
    if (t < b) {
        while (atomicAdd(&g_bflag[t], 0) == 0) {}
        __threadfence();
        contrib = g_bsum[t];
    }
    #pragma unroll
    for (int o = 16; o > 0; o >>= 1) contrib += __shfl_down_sync(0xFFFFFFFFu, contrib, o);
    if (lane == 0) red[wid] = contrib;
    __syncthreads();
    if (t == 0) {
        int ss = 0;
        #pragma unroll
        for (int w = 0; w < 8; w++) ss += red[w];
        sbase = ss;
    }
    __syncthreads();

    int run = sbase + wbase[wid] + (sc - s);
    #pragma unroll
    for (int j = 0; j < 4; j++) {
        int i = idx0 + j;
        if (i < nb2) g_off[i] = run;
        run += v[j];
    }
}

// ---------------------------------------------------------------------------
// place: g_off doubles as cursor; after this kernel g_off[bin] == bin end.
__global__ void place_kernel(const int* __restrict__ src,
                             const int* __restrict__ dst,
                             int E, int half, int n) {
    int e = blockIdx.x * blockDim.x + threadIdx.x;
    if (e >= E) return;
    int s = __ldg(src + e);
    int d = __ldg(dst + e);
    int bin = (e >= half) ? (n + d) : d;
    int pos = atomicAdd(&g_off[bin], 1);
    g_eidx[pos] = s;
}

// ---------------------------------------------------------------------------
// One warp per bin: broadcast idx loads, MLP-4 independent row loads,
// 4/2/1 remainder ladder. (Proven R11 form — high occupancy, standalone.)
__global__ void gather_kernel(const float* __restrict__ x, int nb2) {
    int bin = blockIdx.x * 8 + (threadIdx.x >> 5);
    if (bin >= nb2) return;
    int lane = threadIdx.x & 31;
    int deg = __ldg(&g_cnt[bin]);
    int off = __ldg(&g_off[bin]) - deg;

    const float2* xp = reinterpret_cast<const float2*>(x);
    float2 a0 = make_float2(0.f, 0.f), a1 = a0, a2 = a0, a3 = a0;

    int i = 0;
    for (; i + 3 < deg; i += 4) {
        int s0 = __ldg(g_eidx + off + i);
        int s1 = __ldg(g_eidx + off + i + 1);
        int s2 = __ldg(g_eidx + off + i + 2);
        int s3 = __ldg(g_eidx + off + i + 3);
        float2 v0 = __ldg(xp + (size_t)s0 * 32 + lane);
        float2 v1 = __ldg(xp + (size_t)s1 * 32 + lane);
        float2 v2 = __ldg(xp + (size_t)s2 * 32 + lane);
        float2 v3 = __ldg(xp + (size_t)s3 * 32 + lane);
        a0.x += v0.x; a0.y += v0.y;
        a1.x += v1.x; a1.y += v1.y;
        a2.x += v2.x; a2.y += v2.y;
        a3.x += v3.x; a3.y += v3.y;
    }
    if (i + 1 < deg) {
        int s0 = __ldg(g_eidx + off + i);
        int s1 = __ldg(g_eidx + off + i + 1);
        float2 v0 = __ldg(xp + (size_t)s0 * 32 + lane);
        float2 v1 = __ldg(xp + (size_t)s1 * 32 + lane);
        a0.x += v0.x; a0.y += v0.y;
        a1.x += v1.x; a1.y += v1.y;
        i += 2;
    }
    if (i < deg) {
        int s0 = __ldg(g_eidx + off + i);
        float2 v0 = __ldg(xp + (size_t)s0 * 32 + lane);
        a0.x += v0.x; a0.y += v0.y;
    }
    a0.x += a1.x + a2.x + a3.x;
    a0.y += a1.y + a2.y + a3.y;
    reinterpret_cast<float2*>(g_acc + (size_t)bin * D)[lane] = a0;
}

// ---------------------------------------------------------------------------
__device__ __forceinline__ uint32_t sptr(const void* p) {
    return (uint32_t)__cvta_generic_to_shared(p);
}
__device__ __forceinline__ void ldsm_x4(uint32_t& r0, uint32_t& r1, uint32_t& r2, uint32_t& r3,
                                        uint32_t addr) {
    asm volatile("ldmatrix.sync.aligned.m8n8.x4.shared.b16 {%0,%1,%2,%3}, [%4];"
                 : "=r"(r0), "=r"(r1), "=r"(r2), "=r"(r3) : "r"(addr));
}
__device__ __forceinline__ void ldsm_x4_t(uint32_t& r0, uint32_t& r1, uint32_t& r2, uint32_t& r3,
                                          uint32_t addr) {
    asm volatile("ldmatrix.sync.aligned.m8n8.x4.trans.shared.b16 {%0,%1,%2,%3}, [%4];"
                 : "=r"(r0), "=r"(r1), "=r"(r2), "=r"(r3) : "r"(addr));
}
__device__ __forceinline__ void mma_bf16(float* c, uint32_t a0, uint32_t a1, uint32_t a2, uint32_t a3,
                                         uint32_t b0, uint32_t b1) {
    asm volatile("mma.sync.aligned.m16n8k16.row.col.f32.bf16.bf16.f32 "
                 "{%0,%1,%2,%3}, {%4,%5,%6,%7}, {%8,%9}, {%0,%1,%2,%3};"
                 : "+f"(c[0]), "+f"(c[1]), "+f"(c[2]), "+f"(c[3])
                 : "r"(a0), "r"(a1), "r"(a2), "r"(a3), "r"(b0), "r"(b1));
}

// ---------------------------------------------------------------------------
// Tensor-core node kernel (R11 structure, MT=128 / 256 threads / 8 warps).
__global__ void node_mma_kernel(const float* __restrict__ x,
                                const float* __restrict__ r,
                                const float* __restrict__ W_R, const float* __restrict__ b_R,
                                float* __restrict__ out, int n) {
    int tid = threadIdx.x;

    if (blockIdx.x == gridDim.x - 1) {   // r_out block
        if (tid < 64) {
            float acc = b_R[tid];
            const float* wrow = W_R + tid * 64;
            #pragma unroll 8
            for (int k = 0; k < 64; k++) acc += r[k] * wrow[k];
            out[(size_t)n * D + tid] = acc;
        }
        return;
    }

    extern __shared__ __align__(16) char smraw[];
    __nv_bfloat16* WThi = (__nv_bfloat16*)smraw;            // [192][WS]
    __nv_bfloat16* WTlo = WThi + KD * WS;                   // [192][WS]
    __nv_bfloat16* Uhi  = WTlo + KD * WS;                   // [MT][US]
    __nv_bfloat16* Ulo  = Uhi + MT * US;                    // [MT][US]
    float* Ksm = (float*)(Ulo + MT * US);                   // [64] then bOs, bIs
    float* bOs = Ksm + 64;
    float* bIs = bOs + 64;
    float* cOs = bIs + 64;                                  // [MT]
    float* cIs = cOs + MT;                                  // [MT]

    int node0 = blockIdx.x * MT;

    // ---- stage prepped split weights: straight uint4 copy (256 threads) ----
    {
        const uint4* srcw = reinterpret_cast<const uint4*>(g_wt);
        uint4* dstw = reinterpret_cast<uint4*>(WThi);       // WThi|WTlo contiguous
        #pragma unroll 4
        for (int i = tid; i < (2 * KD * WS) / 8; i += 256) dstw[i] = srcw[i];
    }
    if (tid < 192) Ksm[tid] = g_const[tid];                 // Ksm|bOs|bIs contiguous
    if (tid < MT) {
        int nn = node0 + tid;
        cOs[tid] = (nn < n) ? (float)g_cnt[nn] : 0.f;
        cIs[tid] = (nn < n) ? (float)g_cnt[n + nn] : 0.f;
    }

    // ---- stage U tile with truncation split: 2 threads per row (256 thr / 128 rows) ----
    {
        int nl = tid >> 1;           // 0..127
        int h  = tid & 1;
        int nn = node0 + nl;
        float cO = 0.f, cI = 0.f;
        if (nn < n) {
            cO = (float)g_cnt[nn];
            cI = (float)g_cnt[n + nn];
        }
        const float4* xr = reinterpret_cast<const float4*>(x + (size_t)nn * D);
        const float4* ao = reinterpret_cast<const float4*>(g_acc + (size_t)nn * D);
        const float4* ai = reinterpret_cast<const float4*>(g_acc + ((size_t)n + nn) * D);
        uint32_t* UhiR = reinterpret_cast<uint32_t*>(Uhi + nl * US);
        uint32_t* UloR = reinterpret_cast<uint32_t*>(Ulo + nl * US);
        const float4 z4 = make_float4(0.f, 0.f, 0.f, 0.f);

        #pragma unroll
        for (int q = h * 8; q < h * 8 + 8; q++) {
            float4 vx = z4, vo = z4, vi = z4;
            if (nn < n) {
                vx = __ldg(xr + q);
                vo = ao[q];
                vi = ai[q];
            }
            vo.x -= cO * vx.x; vo.y -= cO * vx.y; vo.z -= cO * vx.z; vo.w -= cO * vx.w;
            vi.x -= cI * vx.x; vi.y -= cI * vx.y; vi.z -= cI * vx.z; vi.w -= cI * vx.w;
            int k2 = q * 2;
            uint32_t hh, ll;
            tsplit2(vx.x, vx.y, hh, ll); UhiR[k2] = hh;          UloR[k2] = ll;
            tsplit2(vx.z, vx.w, hh, ll); UhiR[k2 + 1] = hh;      UloR[k2 + 1] = ll;
            tsplit2(vo.x, vo.y, hh, ll); UhiR[32 + k2] = hh;     UloR[32 + k2] = ll;
            tsplit2(vo.z, vo.w, hh, ll); UhiR[32 + k2 + 1] = hh; UloR[32 + k2 + 1] = ll;
            tsplit2(vi.x, vi.y, hh, ll); UhiR[64 + k2] = hh;     UloR[64 + k2] = ll;
            tsplit2(vi.z, vi.w, hh, ll); UhiR[64 + k2 + 1] = hh; UloR[64 + k2 + 1] = ll;
        }
    }
    __syncthreads();

    // ---- MMA mainloop (8 warps, warp = 16 rows) ----
    int warp = tid >> 5, lane = tid & 31;
    int wr0 = warp * 16;

    float acc[8][4];
    #pragma unroll
    for (int i = 0; i < 8; i++)
        #pragma unroll
        for (int j = 0; j < 4; j++) acc[i][j] = 0.f;

    int lrow = lane & 15;
    int lcol = (lane >> 4) * 8;
    uint32_t aHiBase = sptr(Uhi + (wr0 + lrow) * US + lcol);
    uint32_t aLoBase = sptr(Ulo + (wr0 + lrow) * US + lcol);
    uint32_t bHiBase = sptr(WThi + lrow * WS + lcol);
    uint32_t bLoBase = sptr(WTlo + lrow * WS + lcol);

    for (int ks = 0; ks < KD / 16; ks++) {
        uint32_t koffA = ks * 16 * 2;
        uint32_t koffB = (uint32_t)(ks * 16 * WS) * 2;

        uint32_t ah0, ah1, ah2, ah3, al0, al1, al2, al3;
        ldsm_x4(ah0, ah1, ah2, ah3, aHiBase + koffA);
        ldsm_x4(al0, al1, al2, al3, aLoBase + koffA);

        uint32_t bh[4][4], bl[4][4];
        #pragma unroll
        for (int p = 0; p < 4; p++) {
            uint32_t cofs = (uint32_t)(p * 16) * 2;
            ldsm_x4_t(bh[p][0], bh[p][1], bh[p][2], bh[p][3], bHiBase + koffB + cofs);
            ldsm_x4_t(bl[p][0], bl[p][1], bl[p][2], bl[p][3], bLoBase + koffB + cofs);
        }

        #pragma unroll
        for (int p = 0; p < 4; p++) {
            mma_bf16(acc[2 * p],     ah0, ah1, ah2, ah3, bh[p][0], bh[p][1]);
            mma_bf16(acc[2 * p + 1], ah0, ah1, ah2, ah3, bh[p][2], bh[p][3]);
        }
        #pragma unroll
        for (int p = 0; p < 4; p++) {
            mma_bf16(acc[2 * p],     ah0, ah1, ah2, ah3, bl[p][0], bl[p][1]);
            mma_bf16(acc[2 * p + 1], ah0, ah1, ah2, ah3, bl[p][2], bl[p][3]);
        }
        #pragma unroll
        for (int p = 0; p < 4; p++) {
            mma_bf16(acc[2 * p],     al0, al1, al2, al3, bh[p][0], bh[p][1]);
            mma_bf16(acc[2 * p + 1], al0, al1, al2, al3, bh[p][2], bh[p][3]);
        }
    }

    // ---- epilogue ----
    int rl0 = wr0 + (lane >> 2);
    int rl1 = rl0 + 8;
    int nn0 = node0 + rl0;
    int nn1 = node0 + rl1;
    float cO0 = cOs[rl0], cI0 = cIs[rl0];
    float cO1 = cOs[rl1], cI1 = cIs[rl1];
    int ecol = (lane & 3) * 2;

    #pragma unroll
    for (int nt = 0; nt < 8; nt++) {
        int c = nt * 8 + ecol;
        float k0v = Ksm[c],  k1v = Ksm[c + 1];
        float bo0 = bOs[c],  bo1 = bOs[c + 1];
        float bi0 = bIs[c],  bi1 = bIs[c + 1];
        if (nn0 < n) {
            float2 o;
            o.x = acc[nt][0] + k0v + cO0 * bo0 + cI0 * bi0;
            o.y = acc[nt][1] + k1v + cO0 * bo1 + cI0 * bi1;
            *reinterpret_cast<float2*>(out + (size_t)nn0 * D + c) = o;
        }
        if (nn1 < n) {
            float2 o;
            o.x = acc[nt][2] + k0v + cO1 * bo0 + cI1 * bi0;
            o.y = acc[nt][3] + k1v + cO1 * bo1 + cI1 * bi1;
            *reinterpret_cast<float2*>(out + (size_t)nn1 * D + c) = o;
        }
    }
}

// ---------------------------------------------------------------------------
extern "C" void kernel_launch(void* const* d_in, const int* in_sizes, int n_in,
                              void* d_out, int out_size) {
    const float* x   = (const float*)d_in[0];
    const float* r   = (const float*)d_in[1];
    const int*   src = (const int*)d_in[2];
    const int*   dst = (const int*)d_in[3];
    const float* W_O = (const float*)d_in[4];
    const float* b_O = (const float*)d_in[5];
    const float* W_I = (const float*)d_in[6];
    const float* b_I = (const float*)d_in[7];
    const float* W_S = (const float*)d_in[8];
    const float* b_S = (const float*)d_in[9];
    const float* W_R = (const float*)d_in[10];
    const float* b_R = (const float*)d_in[11];
    float* out = (float*)d_out;

    int n = in_sizes[0] / D;       // 100000
    int E = in_sizes[2];           // 1200000
    int half = E / 2;
    int nb2 = 2 * n;
    int nscan = (nb2 + SCAN_BLK - 1) / SCAN_BLK;   // 196

    const int SMEM_BYTES = (2 * KD * WS + 2 * MT * US) * (int)sizeof(__nv_bfloat16)
                         + (192 + 2 * MT) * (int)sizeof(float);
    cudaFuncSetAttribute(node_mma_kernel, cudaFuncAttributeMaxDynamicSharedMemorySize, SMEM_BYTES);

    int zblocks = (nb2 / 4 + 255) / 256;           // int4-zero blocks
    init_kernel<<<4 + zblocks, 256>>>(W_O, W_I, W_S, b_O, b_I, b_S, r, nb2);
    hist_kernel<<<(E + 255) / 256, 256>>>(dst, E, half, n);
    scan_fused<<<nscan, 256>>>(nb2);
    place_kernel<<<(E + 255) / 256, 256>>>(src, dst, E, half, n);
    gather_kernel<<<(nb2 + 7) / 8, 256>>>(x, nb2);

    int nblocks = (n + MT - 1) / MT + 1;   // +1 for r_out
    node_mma_kernel<<<nblocks, 256, SMEM_BYTES>>>(x, r, W_R, b_R, out, n);
}

// round 14
// speedup vs baseline: 1.6209x; 1.0291x over previous
#include <cuda_runtime.h>
#include <cuda_bf16.h>
#include <cstdint>

#define MAXN 100000
#define MAXE 1200000
#define D 64
#define KD 192
#define MT 128            // node-tile rows per iteration (8 warps x 16 rows)
#define US 200            // Uhi/Ulo row stride in bf16 (192 + 8 pad)
#define WS 72             // WT row stride in bf16 (64 + 8 pad)
#define SCAN_BLK 1024

// Scratch
__device__ float g_acc[2UL * MAXN * D];   // gather results [2][N][64]
__device__ __align__(16) int g_cnt[2 * MAXN];   // per-(half,node) degree
__device__ int   g_off[2 * MAXN];         // scan offsets; after place: bin end
__device__ int   g_eidx[MAXE];            // CSR: src index per edge slot
__device__ int   g_bsum[256];             // scan block aggregates
__device__ int   g_bflag[256];            // aggregate-published flags
__device__ __align__(16) __nv_bfloat16 g_wt[2 * KD * WS];  // [hi|lo] weight tiles
__device__ float g_const[192];            // [K(64) | bO(64) | bI(64)]

// ---------------------------------------------------------------------------
// Truncation bf16 split of a float pair -> packed hi (bf16x2) and lo (bf16x2).
__device__ __forceinline__ void tsplit2(float a, float b, uint32_t& hi, uint32_t& lo) {
    uint32_t ha = __float_as_uint(a) & 0xFFFF0000u;
    uint32_t hb = __float_as_uint(b) & 0xFFFF0000u;
    float la = a - __uint_as_float(ha);
    float lb = b - __uint_as_float(hb);
    hi = __byte_perm(ha, hb, 0x7632);
    lo = __byte_perm(__float_as_uint(la), __float_as_uint(lb), 0x7632);
}

// ---------------------------------------------------------------------------
// Fused init: blocks 0-2 split weights, block 3 consts+flags, block 4 r_out,
// blocks 5+ zero g_cnt.
__global__ void init_kernel(const float* __restrict__ W_O, const float* __restrict__ W_I,
                            const float* __restrict__ W_S,
                            const float* __restrict__ b_O, const float* __restrict__ b_I,
                            const float* __restrict__ b_S, const float* __restrict__ r,
                            const float* __restrict__ W_R, const float* __restrict__ b_R,
                            float* __restrict__ out, int n, int nb2) {
    int b = blockIdx.x;
    int t = threadIdx.x;
    if (b < 3) {
        const float* W = (b == 0) ? W_S : (b == 1) ? W_O : W_I;
        unsigned short* gw = reinterpret_cast<unsigned short*>(g_wt);
        for (int idx = t; idx < 1024; idx += 256) {
            int d = idx >> 4, q = idx & 15;
            float4 w = __ldg(reinterpret_cast<const float4*>(W + d * 64) + q);
            int kb = b * 64 + q * 4;
            float vs[4] = { w.x, w.y, w.z, w.w };
            #pragma unroll
            for (int j = 0; j < 4; j++) {
                uint32_t h = __float_as_uint(vs[j]) & 0xFFFF0000u;
                float l = vs[j] - __uint_as_float(h);
                gw[(kb + j) * WS + d] = (unsigned short)(h >> 16);
                gw[KD * WS + (kb + j) * WS + d] = (unsigned short)(__float_as_uint(l) >> 16);
            }
        }
    } else if (b == 3) {
        g_bflag[t] = 0;                      // reset lookback flags every call
        if (t < 64) {
            float acc = b_S[t];
            const float* wrow = W_S + t * 64;
            #pragma unroll 8
            for (int k = 0; k < 64; k++) acc -= r[k] * wrow[k];
            g_const[t] = acc;
        } else if (t < 128) {
            g_const[t] = b_O[t - 64];
        } else if (t < 192) {
            g_const[t] = b_I[t - 128];
        }
    } else if (b == 4) {
        if (t < 64) {                        // r_out: independent of edge pipeline
            float acc = b_R[t];
            const float* wrow = W_R + t * 64;
            #pragma unroll 8
            for (int k = 0; k < 64; k++) acc += r[k] * wrow[k];
            out[(size_t)n * D + t] = acc;
        }
    } else {
        int i4 = (b - 5) * 256 + t;          // int4 index
        int4* c4 = reinterpret_cast<int4*>(g_cnt);
        if (i4 * 4 < nb2) c4[i4] = make_int4(0, 0, 0, 0);
    }
}

// ---------------------------------------------------------------------------
__global__ void hist_kernel(const int* __restrict__ dst, int E, int half, int n) {
    int e = blockIdx.x * blockDim.x + threadIdx.x;
    if (e >= E) return;
    int d = __ldg(dst + e);
    int bin = (e >= half) ? (n + d) : d;
    atomicAdd(&g_cnt[bin], 1);
}

// ---------------------------------------------------------------------------
// Fused single-pass scan (decoupled lookback, publish-before-wait).
__global__ void scan_fused(int nb2) {
    __shared__ int warp_sums[8];
    __shared__ int wbase[8];
    __shared__ int red[8];
    __shared__ int sbase;
    int t = threadIdx.x;
    int b = blockIdx.x;
    int lane = t & 31, wid = t >> 5;
    int base = b * SCAN_BLK;
    int idx0 = base + t * 4;

    int v[4];
    #pragma unroll
    for (int j = 0; j < 4; j++) {
        int i = idx0 + j;
        v[j] = (i < nb2) ? g_cnt[i] : 0;
    }
    int s = v[0] + v[1] + v[2] + v[3];
    int sc = s;
    #pragma unroll
    for (int o = 1; o < 32; o <<= 1) {
        int u = __shfl_up_sync(0xFFFFFFFFu, sc, o);
        if (lane >= o) sc += u;
    }
    if (lane == 31) warp_sums[wid] = sc;
    __syncthreads();
    if (t == 0) {
        int run = 0;
        #pragma unroll
        for (int w = 0; w < 8; w++) { wbase[w] = run; run += warp_sums[w]; }
        g_bsum[b] = run;
        __threadfence();
        atomicExch(&g_bflag[b], 1);          // publish aggregate
    }

    int contrib = 0;
    if (t < b) {
        while (atomicAdd(&g_bflag[t], 0) == 0) {}
        __threadfence();
        contrib = g_bsum[t];
    }
    #pragma unroll
    for (int o = 16; o > 0; o >>= 1) contrib += __shfl_down_sync(0xFFFFFFFFu, contrib, o);
    if (lane == 0) red[wid] = contrib;
    __syncthreads();
    if (t == 0) {
        int ss = 0;
        #pragma unroll
        for (int w = 0; w < 8; w++) ss += red[w];
        sbase = ss;
    }
    __syncthreads();

    int run = sbase + wbase[wid] + (sc - s);
    #pragma unroll
    for (int j = 0; j < 4; j++) {
        int i = idx0 + j;
        if (i < nb2) g_off[i] = run;
        run += v[j];
    }
}

// ---------------------------------------------------------------------------
// place: g_off doubles as cursor; after this kernel g_off[bin] == bin end.
__global__ void place_kernel(const int* __restrict__ src,
                             const int* __restrict__ dst,
                             int E, int half, int n) {
    int e = blockIdx.x * blockDim.x + threadIdx.x;
    if (e >= E) return;
    int s = __ldg(src + e);
    int d = __ldg(dst + e);
    int bin = (e >= half) ? (n + d) : d;
    int pos = atomicAdd(&g_off[bin], 1);
    g_eidx[pos] = s;
}

// ---------------------------------------------------------------------------
// One warp per bin: broadcast idx loads, MLP-4 independent row loads,
// 4/2/1 remainder ladder. (Proven R11 form — high occupancy, standalone.)
__global__ void gather_kernel(const float* __restrict__ x, int nb2) {
    int bin = blockIdx.x * 8 + (threadIdx.x >> 5);
    if (bin >= nb2) return;
    int lane = threadIdx.x & 31;
    int deg = __ldg(&g_cnt[bin]);
    int off = __ldg(&g_off[bin]) - deg;

    const float2* xp = reinterpret_cast<const float2*>(x);
    float2 a0 = make_float2(0.f, 0.f), a1 = a0, a2 = a0, a3 = a0;

    int i = 0;
    for (; i + 3 < deg; i += 4) {
        int s0 = __ldg(g_eidx + off + i);
        int s1 = __ldg(g_eidx + off + i + 1);
        int s2 = __ldg(g_eidx + off + i + 2);
        int s3 = __ldg(g_eidx + off + i + 3);
        float2 v0 = __ldg(xp + (size_t)s0 * 32 + lane);
        float2 v1 = __ldg(xp + (size_t)s1 * 32 + lane);
        float2 v2 = __ldg(xp + (size_t)s2 * 32 + lane);
        float2 v3 = __ldg(xp + (size_t)s3 * 32 + lane);
        a0.x += v0.x; a0.y += v0.y;
        a1.x += v1.x; a1.y += v1.y;
        a2.x += v2.x; a2.y += v2.y;
        a3.x += v3.x; a3.y += v3.y;
    }
    if (i + 1 < deg) {
        int s0 = __ldg(g_eidx + off + i);
        int s1 = __ldg(g_eidx + off + i + 1);
        float2 v0 = __ldg(xp + (size_t)s0 * 32 + lane);
        float2 v1 = __ldg(xp + (size_t)s1 * 32 + lane);
        a0.x += v0.x; a0.y += v0.y;
        a1.x += v1.x; a1.y += v1.y;
        i += 2;
    }
    if (i < deg) {
        int s0 = __ldg(g_eidx + off + i);
        float2 v0 = __ldg(xp + (size_t)s0 * 32 + lane);
        a0.x += v0.x; a0.y += v0.y;
    }
    a0.x += a1.x + a2.x + a3.x;
    a0.y += a1.y + a2.y + a3.y;
    reinterpret_cast<float2*>(g_acc + (size_t)bin * D)[lane] = a0;
}

// ---------------------------------------------------------------------------
__device__ __forceinline__ uint32_t sptr(const void* p) {
    return (uint32_t)__cvta_generic_to_shared(p);
}
__device__ __forceinline__ void ldsm_x4(uint32_t& r0, uint32_t& r1, uint32_t& r2, uint32_t& r3,
                                        uint32_t addr) {
    asm volatile("ldmatrix.sync.aligned.m8n8.x4.shared.b16 {%0,%1,%2,%3}, [%4];"
                 : "=r"(r0), "=r"(r1), "=r"(r2), "=r"(r3) : "r"(addr));
}
__device__ __forceinline__ void ldsm_x4_t(uint32_t& r0, uint32_t& r1, uint32_t& r2, uint32_t& r3,
                                          uint32_t addr) {
    asm volatile("ldmatrix.sync.aligned.m8n8.x4.trans.shared.b16 {%0,%1,%2,%3}, [%4];"
                 : "=r"(r0), "=r"(r1), "=r"(r2), "=r"(r3) : "r"(addr));
}
__device__ __forceinline__ void mma_bf16(float* c, uint32_t a0, uint32_t a1, uint32_t a2, uint32_t a3,
                                         uint32_t b0, uint32_t b1) {
    asm volatile("mma.sync.aligned.m16n8k16.row.col.f32.bf16.bf16.f32 "
                 "{%0,%1,%2,%3}, {%4,%5,%6,%7}, {%8,%9}, {%0,%1,%2,%3};"
                 : "+f"(c[0]), "+f"(c[1]), "+f"(c[2]), "+f"(c[3])
                 : "r"(a0), "r"(a1), "r"(a2), "r"(a3), "r"(b0), "r"(b1));
}

// ---------------------------------------------------------------------------
// PERSISTENT tensor-core node kernel: weights staged once per CTA (one per SM),
// then loop over node tiles. Structure per tile identical to proven R13 form.
__global__ void node_mma_kernel(const float* __restrict__ x,
                                float* __restrict__ out, int n, int ntiles) {
    int tid = threadIdx.x;

    extern __shared__ __align__(16) char smraw[];
    __nv_bfloat16* WThi = (__nv_bfloat16*)smraw;            // [192][WS]
    __nv_bfloat16* WTlo = WThi + KD * WS;                   // [192][WS]
    __nv_bfloat16* Uhi  = WTlo + KD * WS;                   // [MT][US]
    __nv_bfloat16* Ulo  = Uhi + MT * US;                    // [MT][US]
    float* Ksm = (float*)(Ulo + MT * US);                   // [64] then bOs, bIs
    float* bOs = Ksm + 64;
    float* bIs = bOs + 64;
    float* cOs = bIs + 64;                                  // [MT]
    float* cIs = cOs + MT;                                  // [MT]

    // ---- one-time staging: prepped split weights + consts ----
    {
        const uint4* srcw = reinterpret_cast<const uint4*>(g_wt);
        uint4* dstw = reinterpret_cast<uint4*>(WThi);       // WThi|WTlo contiguous
        #pragma unroll 4
        for (int i = tid; i < (2 * KD * WS) / 8; i += 256) dstw[i] = srcw[i];
    }
    if (tid < 192) Ksm[tid] = g_const[tid];                 // Ksm|bOs|bIs contiguous
    __syncthreads();

    int warp = tid >> 5, lane = tid & 31;
    int wr0 = warp * 16;
    int lrow = lane & 15;
    int lcol = (lane >> 4) * 8;
    uint32_t aHiBase = sptr(Uhi + (wr0 + lrow) * US + lcol);
    uint32_t aLoBase = sptr(Ulo + (wr0 + lrow) * US + lcol);
    uint32_t bHiBase = sptr(WThi + lrow * WS + lcol);
    uint32_t bLoBase = sptr(WTlo + lrow * WS + lcol);

    for (int tile = blockIdx.x; tile < ntiles; tile += gridDim.x) {
        int node0 = tile * MT;

        // ---- stage counts + U tile (trunc split, 2 threads per row) ----
        if (tid < MT) {
            int nn = node0 + tid;
            cOs[tid] = (nn < n) ? (float)g_cnt[nn] : 0.f;
            cIs[tid] = (nn < n) ? (float)g_cnt[n + nn] : 0.f;
        }
        {
            int nl = tid >> 1;           // 0..127
            int h  = tid & 1;
            int nn = node0 + nl;
            float cO = 0.f, cI = 0.f;
            if (nn < n) {
                cO = (float)g_cnt[nn];
                cI = (float)g_cnt[n + nn];
            }
            const float4* xr = reinterpret_cast<const float4*>(x + (size_t)nn * D);
            const float4* ao = reinterpret_cast<const float4*>(g_acc + (size_t)nn * D);
            const float4* ai = reinterpret_cast<const float4*>(g_acc + ((size_t)n + nn) * D);
            uint32_t* UhiR = reinterpret_cast<uint32_t*>(Uhi + nl * US);
            uint32_t* UloR = reinterpret_cast<uint32_t*>(Ulo + nl * US);
            const float4 z4 = make_float4(0.f, 0.f, 0.f, 0.f);

            #pragma unroll
            for (int q = h * 8; q < h * 8 + 8; q++) {
                float4 vx = z4, vo = z4, vi = z4;
                if (nn < n) {
                    vx = __ldg(xr + q);
                    vo = ao[q];
                    vi = ai[q];
                }
                vo.x -= cO * vx.x; vo.y -= cO * vx.y; vo.z -= cO * vx.z; vo.w -= cO * vx.w;
                vi.x -= cI * vx.x; vi.y -= cI * vx.y; vi.z -= cI * vx.z; vi.w -= cI * vx.w;
                int k2 = q * 2;
                uint32_t hh, ll;
                tsplit2(vx.x, vx.y, hh, ll); UhiR[k2] = hh;          UloR[k2] = ll;
                tsplit2(vx.z, vx.w, hh, ll); UhiR[k2 + 1] = hh;      UloR[k2 + 1] = ll;
                tsplit2(vo.x, vo.y, hh, ll); UhiR[32 + k2] = hh;     UloR[32 + k2] = ll;
                tsplit2(vo.z, vo.w, hh, ll); UhiR[32 + k2 + 1] = hh; UloR[32 + k2 + 1] = ll;
                tsplit2(vi.x, vi.y, hh, ll); UhiR[64 + k2] = hh;     UloR[64 + k2] = ll;
                tsplit2(vi.z, vi.w, hh, ll); UhiR[64 + k2 + 1] = hh; UloR[64 + k2 + 1] = ll;
            }
        }
        __syncthreads();

        // ---- MMA mainloop (8 warps, warp = 16 rows) ----
        float acc[8][4];
        #pragma unroll
        for (int i = 0; i < 8; i++)
            #pragma unroll
            for (int j = 0; j < 4; j++) acc[i][j] = 0.f;

        for (int ks = 0; ks < KD / 16; ks++) {
            uint32_t koffA = ks * 16 * 2;
            uint32_t koffB = (uint32_t)(ks * 16 * WS) * 2;

            uint32_t ah0, ah1, ah2, ah3, al0, al1, al2, al3;
            ldsm_x4(ah0, ah1, ah2, ah3, aHiBase + koffA);
            ldsm_x4(al0, al1, al2, al3, aLoBase + koffA);

            uint32_t bh[4][4], bl[4][4];
            #pragma unroll
            for (int p = 0; p < 4; p++) {
                uint32_t cofs = (uint32_t)(p * 16) * 2;
                ldsm_x4_t(bh[p][0], bh[p][1], bh[p][2], bh[p][3], bHiBase + koffB + cofs);
                ldsm_x4_t(bl[p][0], bl[p][1], bl[p][2], bl[p][3], bLoBase + koffB + cofs);
            }

            #pragma unroll
            for (int p = 0; p < 4; p++) {
                mma_bf16(acc[2 * p],     ah0, ah1, ah2, ah3, bh[p][0], bh[p][1]);
                mma_bf16(acc[2 * p + 1], ah0, ah1, ah2, ah3, bh[p][2], bh[p][3]);
            }
            #pragma unroll
            for (int p = 0; p < 4; p++) {
                mma_bf16(acc[2 * p],     ah0, ah1, ah2, ah3, bl[p][0], bl[p][1]);
                mma_bf16(acc[2 * p + 1], ah0, ah1, ah2, ah3, bl[p][2], bl[p][3]);
            }
            #pragma unroll
            for (int p = 0; p < 4; p++) {
                mma_bf16(acc[2 * p],     al0, al1, al2, al3, bh[p][0], bh[p][1]);
                mma_bf16(acc[2 * p + 1], al0, al1, al2, al3, bh[p][2], bh[p][3]);
            }
        }

        // ---- epilogue ----
        int rl0 = wr0 + (lane >> 2);
        int rl1 = rl0 + 8;
        int nn0 = node0 + rl0;
        int nn1 = node0 + rl1;
        float cO0 = cOs[rl0], cI0 = cIs[rl0];
        float cO1 = cOs[rl1], cI1 = cIs[rl1];
        int ecol = (lane & 3) * 2;

        #pragma unroll
        for (int nt = 0; nt < 8; nt++) {
            int c = nt * 8 + ecol;
            float k0v = Ksm[c],  k1v = Ksm[c + 1];
            float bo0 = bOs[c],  bo1 = bOs[c + 1];
            float bi0 = bIs[c],  bi1 = bIs[c + 1];
            if (nn0 < n) {
                float2 o;
                o.x = acc[nt][0] + k0v + cO0 * bo0 + cI0 * bi0;
                o.y = acc[nt][1] + k1v + cO0 * bo1 + cI0 * bi1;
                *reinterpret_cast<float2*>(out + (size_t)nn0 * D + c) = o;
            }
            if (nn1 < n) {
                float2 o;
                o.x = acc[nt][2] + k0v + cO1 * bo0 + cI1 * bi0;
                o.y = acc[nt][3] + k1v + cO1 * bo1 + cI1 * bi1;
                *reinterpret_cast<float2*>(out + (size_t)nn1 * D + c) = o;
            }
        }
        __syncthreads();   // protect U/cOs before next tile's staging
    }
}

// ---------------------------------------------------------------------------
extern "C" void kernel_launch(void* const* d_in, const int* in_sizes, int n_in,
                              void* d_out, int out_size) {
    const float* x   = (const float*)d_in[0];
    const float* r   = (const float*)d_in[1];
    const int*   src = (const int*)d_in[2];
    const int*   dst = (const int*)d_in[3];
    const float* W_O = (const float*)d_in[4];
    const float* b_O = (const float*)d_in[5];
    const float* W_I = (const float*)d_in[6];
    const float* b_I = (const float*)d_in[7];
    const float* W_S = (const float*)d_in[8];
    const float* b_S = (const float*)d_in[9];
    const float* W_R = (const float*)d_in[10];
    const float* b_R = (const float*)d_in[11];
    float* out = (float*)d_out;

    int n = in_sizes[0] / D;       // 100000
    int E = in_sizes[2];           // 1200000
    int half = E / 2;
    int nb2 = 2 * n;
    int nscan = (nb2 + SCAN_BLK - 1) / SCAN_BLK;   // 196

    const int SMEM_BYTES = (2 * KD * WS + 2 * MT * US) * (int)sizeof(__nv_bfloat16)
                         + (192 + 2 * MT) * (int)sizeof(float);
    cudaFuncSetAttribute(node_mma_kernel, cudaFuncAttributeMaxDynamicSharedMemorySize, SMEM_BYTES);

    int nsm = 148;
    cudaDeviceGetAttribute(&nsm, cudaDevAttrMultiProcessorCount, 0);

    int zblocks = (nb2 / 4 + 255) / 256;           // int4-zero blocks
    init_kernel<<<5 + zblocks, 256>>>(W_O, W_I, W_S, b_O, b_I, b_S, r,
                                      W_R, b_R, out, n, nb2);
    hist_kernel<<<(E + 255) / 256, 256>>>(dst, E, half, n);
    scan_fused<<<nscan, 256>>>(nb2);
    place_kernel<<<(E + 255) / 256, 256>>>(src, dst, E, half, n);
    gather_kernel<<<(nb2 + 7) / 8, 256>>>(x, nb2);

    int ntiles = (n + MT - 1) / MT;                // 782
    int grid = (ntiles < nsm) ? ntiles : nsm;
    node_mma_kernel<<<grid, 256, SMEM_BYTES>>>(x, out, n, ntiles);
}